// round 1
// baseline (speedup 1.0000x reference)
#include <cuda_runtime.h>

// Problem constants
#define A_BATCH   128
#define M_LEN     256
#define D_DIM     16
#define MM        255          // (M-1) grid size of the PDE
#define NTASK     384          // 3 PDE solves x 128 batch
#define PW        64           // panel width (columns)
#define INC_STRIDE 65          // odd stride -> conflict-free diagonal access

// SMEM layout (floats):
//   s_dY  : 255*16   = 4080
//   s_inc : 255*65   = 16575
//   s_buf : 3*256    = 768    (rotating anti-diagonal buffers)
//   s_colK: 256               (panel-boundary column of K)
#define SM_DY    0
#define SM_INC   (SM_DY + MM * D_DIM)
#define SM_BUF   (SM_INC + MM * INC_STRIDE)
#define SM_COLK  (SM_BUF + 3 * 256)
#define SMEM_FLOATS (SM_COLK + 256)
#define SMEM_BYTES  (SMEM_FLOATS * 4)

__device__ float g_partial[NTASK];

// One CTA solves one (pde, batch) signature-kernel PDE on a 255x255 grid.
// Thread t owns row i = t (dX[t] in registers). Columns are processed in
// panels of width PW: phase 1 fills the inc panel in SMEM (broadcast dY
// reads, FMA bound), phase 2 runs the anti-diagonal wavefront over the panel.
__global__ void __launch_bounds__(256, 2) sig_pde_kernel(
    const float* __restrict__ X, const float* __restrict__ Y)
{
    extern __shared__ float smem[];
    float* s_dY   = smem + SM_DY;
    float* s_inc  = smem + SM_INC;
    float* s_buf  = smem + SM_BUF;
    float* s_colK = smem + SM_COLK;

    const int task = blockIdx.x;
    const int pde  = task >> 7;        // 0: (X,X)  1: (Y,Y)  2: (X,Y)
    const int a    = task & 127;
    const float* sX = (pde == 1 ? Y : X) + (size_t)a * M_LEN * D_DIM;
    const float* sY = (pde == 0 ? X : Y) + (size_t)a * M_LEN * D_DIM;

    const int t = threadIdx.x;

    // dY[j][k] = Y[j+1][k] - Y[j][k]   (row-major, stride 16)
    for (int idx = t; idx < MM * D_DIM; idx += 256)
        s_dY[idx] = sY[idx + D_DIM] - sY[idx];

    // dX row for this thread, kept in registers
    float dX[D_DIM];
    if (t < MM) {
#pragma unroll
        for (int k = 0; k < D_DIM; k++)
            dX[k] = sX[(t + 1) * D_DIM + k] - sX[t * D_DIM + k];
    }

    // K[i+1][0] = 1 boundary (left edge of first panel)
    s_colK[t] = 1.0f;
    __syncthreads();

    int j0 = 0;
#pragma unroll 1
    for (int p = 0; p < 4; p++) {
        const int Wp = (MM - j0) < PW ? (MM - j0) : PW;

        // ---------------- phase 1: inc panel = dX[t] . dY[j0+jj] -------------
        if (t < MM) {
            const float4* dy4 = reinterpret_cast<const float4*>(s_dY + j0 * D_DIM);
#pragma unroll 4
            for (int jj = 0; jj < Wp; jj++) {
                float4 y0 = dy4[jj * 4 + 0];
                float4 y1 = dy4[jj * 4 + 1];
                float4 y2 = dy4[jj * 4 + 2];
                float4 y3 = dy4[jj * 4 + 3];
                float acc;
                acc  = dX[0]  * y0.x; acc += dX[1]  * y0.y;
                acc += dX[2]  * y0.z; acc += dX[3]  * y0.w;
                acc += dX[4]  * y1.x; acc += dX[5]  * y1.y;
                acc += dX[6]  * y1.z; acc += dX[7]  * y1.w;
                acc += dX[8]  * y2.x; acc += dX[9]  * y2.y;
                acc += dX[10] * y2.z; acc += dX[11] * y2.w;
                acc += dX[12] * y3.x; acc += dX[13] * y3.y;
                acc += dX[14] * y3.z; acc += dX[15] * y3.w;
                s_inc[t * INC_STRIDE + jj] = acc;
            }
        }
        __syncthreads();

        // ---------------- phase 2: anti-diagonal wavefront -------------------
        // cell (i=t, j=j0+jj) on local diagonal d = t + jj
        //   left = K[t+1][j]   : own previous value (register) or colK at jj==0
        //   up   = K[t][j+1]   : neighbor t-1, diagonal d-1
        //   diag = K[t][j]     : neighbor t-1, diagonal d-2 (or colK at jj==0)
        const int nsteps = MM + Wp - 1;
        float left_reg = 1.0f;
#pragma unroll 1
        for (int d = 0; d < nsteps; d++) {
            const int jj = d - t;
            if (t < MM && jj >= 0 && jj < Wp) {
                const float g = s_inc[t * INC_STRIDE + jj];
                const float left = (jj == 0) ? s_colK[t] : left_reg;
                float up, diag;
                if (t == 0) {
                    up = 1.0f; diag = 1.0f;
                } else {
                    up   = s_buf[((d + 2) % 3) * 256 + (t - 1)];   // diagonal d-1
                    diag = (jj == 0) ? s_colK[t - 1]
                                     : s_buf[((d + 1) % 3) * 256 + (t - 1)]; // d-2
                }
                const float gg = g * g * (1.0f / 12.0f);
                const float c1 = 1.0f + 0.5f * g + gg;
                const float c2 = 1.0f - gg;
                const float knew = (left + up) * c1 - diag * c2;
                left_reg = knew;
                s_buf[(d % 3) * 256 + t] = knew;
                if (jj == Wp - 1) s_colK[t] = knew;   // carry panel boundary
            }
            __syncthreads();
        }
        j0 += Wp;
    }

    // K[255][255] = colK[254] after the last panel
    if (t == 0) g_partial[task] = s_colK[MM - 1];
}

// mean(kXX) + mean(kYY) - 2*mean(kXY)
__global__ void reduce_kernel(float* __restrict__ out)
{
    __shared__ float s[512];
    const int t = threadIdx.x;
    float v = 0.0f;
    if (t < NTASK) {
        const float w = (t >= 256) ? -2.0f : 1.0f;
        v = w * g_partial[t];
    }
    s[t] = v;
    __syncthreads();
#pragma unroll
    for (int off = 256; off > 0; off >>= 1) {
        if (t < off) s[t] += s[t + off];
        __syncthreads();
    }
    if (t == 0) out[0] = s[0] * (1.0f / (float)A_BATCH);
}

extern "C" void kernel_launch(void* const* d_in, const int* in_sizes, int n_in,
                              void* d_out, int out_size)
{
    const float* X = (const float*)d_in[0];
    const float* Y = (const float*)d_in[1];
    float* out = (float*)d_out;

    cudaFuncSetAttribute(sig_pde_kernel,
                         cudaFuncAttributeMaxDynamicSharedMemorySize, SMEM_BYTES);

    sig_pde_kernel<<<NTASK, 256, SMEM_BYTES>>>(X, Y);
    reduce_kernel<<<1, 512>>>(out);
}

// round 2
// speedup vs baseline: 3.0381x; 3.0381x over previous
#include <cuda_runtime.h>

// Problem constants
#define A_BATCH   128
#define M_LEN     256
#define D_DIM     16
#define MM        255          // (M-1) PDE grid size
#define NTASK     384          // 3 PDE solves x 128 batch
#define PW        64           // panel width (columns)
#define INC_STRIDE 65          // odd stride -> conflict-free scattered access

// SMEM layout (floats):
//   s_dY  : 255*16        = 4080
//   s_inc : 256*65        = 16640   (row 255 zero pad for lane-31 r=7 junk cell)
#define SM_DY    0
#define SM_INC   (SM_DY + MM * D_DIM)
#define SMEM_FLOATS (SM_INC + 256 * INC_STRIDE)
#define SMEM_BYTES  (SMEM_FLOATS * 4)

__device__ float g_partial[NTASK];

// One CTA per (pde, batch) task. Phase 1: 256 threads compute the inc panel
// (g values) into SMEM. Phase 2: warp 0 runs a barrier-free anti-diagonal
// wavefront; lane t owns rows 8t..8t+7, boundary values flow via shfl_up.
__global__ void __launch_bounds__(256, 2) sig_pde_kernel(
    const float* __restrict__ X, const float* __restrict__ Y)
{
    extern __shared__ float smem[];
    float* s_dY  = smem + SM_DY;
    float* s_inc = smem + SM_INC;

    const int task = blockIdx.x;
    const int pde  = task >> 7;        // 0:(X,X) 1:(Y,Y) 2:(X,Y)
    const int a    = task & 127;
    const float* sX = (pde == 1 ? Y : X) + (size_t)a * M_LEN * D_DIM;
    const float* sY = (pde == 0 ? X : Y) + (size_t)a * M_LEN * D_DIM;

    const int t = threadIdx.x;

    // dY[j][k] = Y[j+1][k] - Y[j][k]
    for (int idx = t; idx < MM * D_DIM; idx += 256)
        s_dY[idx] = sY[idx + D_DIM] - sY[idx];

    // dX row for this thread (phase-1 use)
    float dX[D_DIM];
    if (t < MM) {
#pragma unroll
        for (int k = 0; k < D_DIM; k++)
            dX[k] = sX[(t + 1) * D_DIM + k] - sX[t * D_DIM + k];
    }
    __syncthreads();

    // Wavefront left-boundary state: L[r] = K[8t+r+1][j0], starts at K[*][0]=1
    float L[8];
#pragma unroll
    for (int r = 0; r < 8; r++) L[r] = 1.0f;

    int j0 = 0;
#pragma unroll 1
    for (int p = 0; p < 4; p++) {
        const int Wp = (MM - j0) < PW ? (MM - j0) : PW;

        // ---------------- phase 1: inc panel = dX[t] . dY[j0+jj] ------------
        if (t < MM) {
            const float4* dy4 = reinterpret_cast<const float4*>(s_dY + j0 * D_DIM);
#pragma unroll 4
            for (int jj = 0; jj < Wp; jj++) {
                float4 y0 = dy4[jj * 4 + 0];
                float4 y1 = dy4[jj * 4 + 1];
                float4 y2 = dy4[jj * 4 + 2];
                float4 y3 = dy4[jj * 4 + 3];
                float acc;
                acc  = dX[0]  * y0.x; acc += dX[1]  * y0.y;
                acc += dX[2]  * y0.z; acc += dX[3]  * y0.w;
                acc += dX[4]  * y1.x; acc += dX[5]  * y1.y;
                acc += dX[6]  * y1.z; acc += dX[7]  * y1.w;
                acc += dX[8]  * y2.x; acc += dX[9]  * y2.y;
                acc += dX[10] * y2.z; acc += dX[11] * y2.w;
                acc += dX[12] * y3.x; acc += dX[13] * y3.y;
                acc += dX[14] * y3.z; acc += dX[15] * y3.w;
                s_inc[t * INC_STRIDE + jj] = acc;
            }
        } else {
            // t == 255: zero-pad row 255 (read by lane 31's junk r=7 cell)
            for (int jj = 0; jj < Wp; jj++)
                s_inc[MM * INC_STRIDE + jj] = 0.0f;
        }
        __syncthreads();

        // ---------------- phase 2: barrier-free warp wavefront --------------
        // Lane t, local column jj = s - t. Cell (i=8t+r, j=j0+jj) computes
        // K[i+1][j+1]:
        //   left = L[r]           (K[i+1][j], register)
        //   diag = L[r-1]         (K[i][j]);  r=0: nb_prev (neighbor boundary)
        //   up   = previous knew  (K[i][j+1]); r=0: nb_new (shfl this step)
        if (t < 32) {
            // neighbor boundary K[8t][j0] = lane (t-1)'s L[7]
            float nb_prev = __shfl_up_sync(0xffffffffu, L[7], 1);
            float last_knew = 0.0f;
            const float* grow = s_inc + t * (8 * INC_STRIDE);
            const int nsteps = 32 + Wp - 1;
#pragma unroll 1
            for (int s = 0; s < nsteps; s++) {
                float nb_new = __shfl_up_sync(0xffffffffu, last_knew, 1);
                const int jj = s - t;
                if (jj >= 0 && jj < Wp) {
                    float c1[8], c2[8], P[8];
#pragma unroll
                    for (int r = 0; r < 8; r++) {
                        const float g  = grow[r * INC_STRIDE + jj];
                        const float gg = g * g * (1.0f / 12.0f);
                        c1[r] = fmaf(g, 0.5f, 1.0f + gg);
                        c2[r] = 1.0f - gg;
                    }
                    const float diag0 = (t == 0) ? 1.0f : nb_prev;
                    const float up0   = (t == 0) ? 1.0f : nb_new;
                    // off-chain partials
                    P[0] = L[0] * c1[0] - diag0 * c2[0];
#pragma unroll
                    for (int r = 1; r < 8; r++)
                        P[r] = L[r] * c1[r] - L[r - 1] * c2[r];
                    // dependent chain: 8 FFMA
                    float k = fmaf(up0, c1[0], P[0]); L[0] = k;
#pragma unroll
                    for (int r = 1; r < 8; r++) {
                        k = fmaf(k, c1[r], P[r]); L[r] = k;
                    }
                    last_knew = k;
                    nb_prev = nb_new;
                }
            }
        }
        __syncthreads();
        j0 += Wp;
    }

    // K[255][255] = L[6] of lane 31 (row i=254 is r=6 of lane 31)
    if (t == 31) g_partial[task] = L[6];
}

// mean(kXX) + mean(kYY) - 2*mean(kXY)
__global__ void reduce_kernel(float* __restrict__ out)
{
    __shared__ float s[512];
    const int t = threadIdx.x;
    float v = 0.0f;
    if (t < NTASK) {
        const float w = (t >= 256) ? -2.0f : 1.0f;
        v = w * g_partial[t];
    }
    s[t] = v;
    __syncthreads();
#pragma unroll
    for (int off = 256; off > 0; off >>= 1) {
        if (t < off) s[t] += s[t + off];
        __syncthreads();
    }
    if (t == 0) out[0] = s[0] * (1.0f / (float)A_BATCH);
}

extern "C" void kernel_launch(void* const* d_in, const int* in_sizes, int n_in,
                              void* d_out, int out_size)
{
    const float* X = (const float*)d_in[0];
    const float* Y = (const float*)d_in[1];
    float* out = (float*)d_out;

    cudaFuncSetAttribute(sig_pde_kernel,
                         cudaFuncAttributeMaxDynamicSharedMemorySize, SMEM_BYTES);

    sig_pde_kernel<<<NTASK, 256, SMEM_BYTES>>>(X, Y);
    reduce_kernel<<<1, 512>>>(out);
}